// round 16
// baseline (speedup 1.0000x reference)
#include <cuda_runtime.h>
#include <cuda_bf16.h>
#include <math.h>

#define BB 16
#define CC 128
#define HW 16384
#define KS1 8
#define KSEG (HW / KS1)  // 2048

__device__ float g_energy[BB * CC * CC];
__device__ float g_epF[BB * KS1 * CC * CC];
__device__ float g_epG[BB * KS1 * CC * CC];
__device__ float g_attn[BB * CC * CC];
__device__ float g_rspart[BB * KS1 * CC];
__device__ float g_part1[BB * CC];
__device__ float g_part2[BB * CC];
// precomputed swizzled q-limb blobs: [b][chunk 256][limb 2][16384 bytes]
__device__ __align__(16) char g_lb[(size_t)BB * 256 * 32768];

__device__ __forceinline__ unsigned smem_u32(const void* p) {
    unsigned a;
    asm("{ .reg .u64 t; cvta.to.shared.u64 t, %1; cvt.u32.u64 %0, t; }" : "=r"(a) : "l"(p));
    return a;
}
__device__ __forceinline__ unsigned swz(unsigned o) { return o ^ ((o >> 3) & 0x70); }

#define CPA(dst, src) asm volatile("cp.async.ca.shared.global [%0], [%1], 16;" :: "r"(dst), "l"(src))
#define CPA_COMMIT()  asm volatile("cp.async.commit_group;" ::: "memory")
#define CPA_WAIT0()   asm volatile("cp.async.wait_group 0;" ::: "memory")
#define CPA_WAIT1()   asm volatile("cp.async.wait_group 1;" ::: "memory")

__device__ __forceinline__ void ldsm4(unsigned a, unsigned r[4]) {
    asm volatile("ldmatrix.sync.aligned.m8n8.x4.shared.b16 {%0,%1,%2,%3}, [%4];"
                 : "=r"(r[0]), "=r"(r[1]), "=r"(r[2]), "=r"(r[3]) : "r"(a));
}
__device__ __forceinline__ void ldsm4t(unsigned a, unsigned r[4]) {
    asm volatile("ldmatrix.sync.aligned.m8n8.x4.trans.shared.b16 {%0,%1,%2,%3}, [%4];"
                 : "=r"(r[0]), "=r"(r[1]), "=r"(r[2]), "=r"(r[3]) : "r"(a));
}
__device__ __forceinline__ void mma16816(float c[4], const unsigned a[4], unsigned b0, unsigned b1) {
    asm volatile("mma.sync.aligned.m16n8k16.row.col.f32.bf16.bf16.f32 "
                 "{%0,%1,%2,%3}, {%4,%5,%6,%7}, {%8,%9}, {%0,%1,%2,%3};"
                 : "+f"(c[0]), "+f"(c[1]), "+f"(c[2]), "+f"(c[3])
                 : "r"(a[0]), "r"(a[1]), "r"(a[2]), "r"(a[3]), "r"(b0), "r"(b1));
}

// packed 2-limb bf16 split (bit-identical to per-scalar __float2bfloat16_rn)
__device__ __forceinline__ void conv8r(const float* fl, char* d0, char* d1) {
    unsigned p[4], q[4];
    #pragma unroll
    for (int k = 0; k < 4; k++) {
        float lo = fl[2 * k], hi = fl[2 * k + 1];
        unsigned pk;
        asm("cvt.rn.bf16x2.f32 %0, %1, %2;" : "=r"(pk) : "f"(hi), "f"(lo));
        float rlo = lo - __uint_as_float(pk << 16);
        float rhi = hi - __uint_as_float(pk & 0xFFFF0000u);
        unsigned qk;
        asm("cvt.rn.bf16x2.f32 %0, %1, %2;" : "=r"(qk) : "f"(rhi), "f"(rlo));
        p[k] = pk; q[k] = qk;
    }
    *(uint4*)d0 = make_uint4(p[0], p[1], p[2], p[3]);
    *(uint4*)d1 = make_uint4(q[0], q[1], q[2], q[3]);
}
// conv + mirror the two 16B limb vectors to global (for out's cp.async path)
__device__ __forceinline__ float conv8g(const char* sp, char* d0, char* d1,
                                        char* g0, char* g1) {
    float4 a = ((const float4*)sp)[0];
    float4 b = ((const float4*)sp)[1];
    float fl[8] = {a.x, a.y, a.z, a.w, b.x, b.y, b.z, b.w};
    unsigned p[4], q[4];
    #pragma unroll
    for (int k = 0; k < 4; k++) {
        float lo = fl[2 * k], hi = fl[2 * k + 1];
        unsigned pk;
        asm("cvt.rn.bf16x2.f32 %0, %1, %2;" : "=r"(pk) : "f"(hi), "f"(lo));
        float rlo = lo - __uint_as_float(pk << 16);
        float rhi = hi - __uint_as_float(pk & 0xFFFF0000u);
        unsigned qk;
        asm("cvt.rn.bf16x2.f32 %0, %1, %2;" : "=r"(qk) : "f"(rhi), "f"(rlo));
        p[k] = pk; q[k] = qk;
    }
    uint4 v0 = make_uint4(p[0], p[1], p[2], p[3]);
    uint4 v1 = make_uint4(q[0], q[1], q[2], q[3]);
    *(uint4*)d0 = v0;
    *(uint4*)d1 = v1;
    *(uint4*)g0 = v0;
    *(uint4*)g1 = v1;
    return ((fl[0] + fl[1]) + (fl[2] + fl[3])) + ((fl[4] + fl[5]) + (fl[6] + fl[7]));
}

// ---- kernel 0: energy + limb-blob export ------------------------------------
__global__ void __launch_bounds__(256) k_energy_mma(const float* __restrict__ x) {
    extern __shared__ char smraw[];
    char* sm = (char*)(((unsigned long long)smraw + 1023) & ~1023ULL);
    unsigned sb = smem_u32(sm);
    int t = threadIdx.x, lane = t & 31, wid = t >> 5;
    int ks = blockIdx.x, b = blockIdx.y;
    size_t rowbase = (size_t)b * CC * HW + (size_t)ks * KSEG;
    int wm = (wid >> 2) * 64, wn = (wid & 3) * 32;
    float* s_rs = (float*)(sm + 131072);
    float rsacc[4] = {0.f, 0.f, 0.f, 0.f};

    float accF[4][4][4], accG[4][4][4];
    #pragma unroll
    for (int mt = 0; mt < 4; mt++)
        #pragma unroll
        for (int nt = 0; nt < 4; nt++)
            #pragma unroll
            for (int c = 0; c < 4; c++) { accF[mt][nt][c] = 0.f; accG[mt][nt][c] = 0.f; }

    #define X_LOAD(ch) do { \
        unsigned _db = sb + ((ch) & 1) * 32768; \
        _Pragma("unroll") \
        for (int _i = 0; _i < 4; _i++) { \
            int _seg = t + 256 * _i; \
            int _row = _seg >> 3, _part = _seg & 7; \
            const float* _s = x + rowbase + (size_t)_row * HW + (ch) * 64 + _part * 8; \
            CPA(_db + _row * 256 + _part * 32, _s); \
            CPA(_db + _row * 256 + _part * 32 + 16, _s + 4); \
        } \
        CPA_COMMIT(); \
    } while (0)

    #define X_CONV(ch) do { \
        char* _st = sm + ((ch) & 1) * 32768; \
        char* _lb = sm + 65536 + ((ch) & 1) * 32768; \
        char* _gb = g_lb + ((size_t)b * 256 + ks * 32 + (ch)) * 32768; \
        _Pragma("unroll") \
        for (int _i = 0; _i < 4; _i++) { \
            int _seg = t + 256 * _i; \
            int _row = _seg >> 3, _part = _seg & 7; \
            unsigned _so = swz((unsigned)(_row * 128 + _part * 16)); \
            rsacc[_i] += conv8g(_st + _row * 256 + _part * 32, _lb + _so, _lb + 16384 + _so, \
                                _gb + _so, _gb + 16384 + _so); \
        } \
    } while (0)

    X_LOAD(0);
    X_LOAD(1);
    CPA_WAIT1();
    X_CONV(0);
    __syncthreads();

    for (int ch = 0; ch < 32; ch++) {
        if (ch + 2 < 32) X_LOAD(ch + 2);

        unsigned b0t = sb + 65536 + (ch & 1) * 32768;
        unsigned b1t = b0t + 16384;
        #pragma unroll
        for (int kk = 0; kk < 4; kk++) {
            int kbyte = kk * 32;
            unsigned A[4][4];
            #pragma unroll
            for (int mt = 0; mt < 4; mt++) {
                unsigned off = swz((unsigned)((wm + mt * 16 + (lane & 15)) * 128 + kbyte + (lane >> 4) * 16));
                ldsm4(b0t + off, A[mt]);
            }
            unsigned B0[2][4], B1[2][4];
            #pragma unroll
            for (int nt = 0; nt < 2; nt++) {
                int row = wn + nt * 16 + ((lane >> 4) & 1) * 8 + (lane & 7);
                int kb = kbyte + ((lane >> 3) & 1) * 16;
                unsigned off = swz((unsigned)(row * 128 + kb));
                ldsm4(b0t + off, B0[nt]);
                ldsm4(b1t + off, B1[nt]);
            }
            #pragma unroll
            for (int mt = 0; mt < 4; mt++)
                #pragma unroll
                for (int nt = 0; nt < 2; nt++)
                    #pragma unroll
                    for (int s = 0; s < 2; s++) {
                        mma16816(accF[mt][nt * 2 + s], A[mt], B0[nt][s * 2], B0[nt][s * 2 + 1]);
                        mma16816(accG[mt][nt * 2 + s], A[mt], B1[nt][s * 2], B1[nt][s * 2 + 1]);
                    }
        }

        if (ch + 1 < 32) {
            if (ch + 2 < 32) CPA_WAIT1(); else CPA_WAIT0();
            X_CONV(ch + 1);
        }
        __syncthreads();
    }
    #undef X_LOAD
    #undef X_CONV

    #pragma unroll
    for (int i = 0; i < 4; i++) s_rs[t + 256 * i] = rsacc[i];
    __syncthreads();
    if (t < 128) {
        float s = 0.f;
        #pragma unroll
        for (int k = 0; k < 8; k++) s += s_rs[t * 8 + k];
        g_rspart[(b * KS1 + ks) * CC + t] = s;
    }

    size_t pbase = ((size_t)(b * KS1 + ks)) * CC * CC;
    int g = lane >> 2, tg = lane & 3;
    #pragma unroll
    for (int mt = 0; mt < 4; mt++)
        #pragma unroll
        for (int nt = 0; nt < 4; nt++) {
            int i0 = wm + mt * 16 + g, j = wn + nt * 8 + tg * 2;
            *(float2*)(g_epF + pbase + (size_t)i0 * CC + j) = make_float2(accF[mt][nt][0], accF[mt][nt][1]);
            *(float2*)(g_epF + pbase + (size_t)(i0 + 8) * CC + j) = make_float2(accF[mt][nt][2], accF[mt][nt][3]);
            *(float2*)(g_epG + pbase + (size_t)i0 * CC + j) = make_float2(accG[mt][nt][0], accG[mt][nt][1]);
            *(float2*)(g_epG + pbase + (size_t)(i0 + 8) * CC + j) = make_float2(accG[mt][nt][2], accG[mt][nt][3]);
        }
}

// ---- kernel 1: fused E = F + G + G^T  AND softmax ---------------------------
__global__ void k_redsoft() {
    int islab = blockIdx.x, b = blockIdx.y, t = threadIdx.x;
    __shared__ float sGT[32][132];
    #pragma unroll
    for (int r = 0; r < 4; r++) {
        int idx = t + 256 * r;
        int j = idx >> 3, c4 = idx & 7;
        float4 s = make_float4(0.f, 0.f, 0.f, 0.f);
        #pragma unroll
        for (int ks = 0; ks < KS1; ks++) {
            float4 v = *(const float4*)(g_epG + (((size_t)(b * KS1 + ks) * CC + j)) * CC + islab * 32 + c4 * 4);
            s.x += v.x; s.y += v.y; s.z += v.z; s.w += v.w;
        }
        sGT[c4 * 4 + 0][j] = s.x;
        sGT[c4 * 4 + 1][j] = s.y;
        sGT[c4 * 4 + 2][j] = s.z;
        sGT[c4 * 4 + 3][j] = s.w;
    }
    __syncthreads();
    #pragma unroll
    for (int r = 0; r < 4; r++) {
        int idx = t + 256 * r;
        int il = idx >> 5, j4 = idx & 31;
        int i = islab * 32 + il;
        float4 f = make_float4(0.f, 0.f, 0.f, 0.f);
        #pragma unroll
        for (int ks = 0; ks < KS1; ks++) {
            size_t o = (((size_t)(b * KS1 + ks) * CC + i)) * CC + j4 * 4;
            float4 vf = *(const float4*)(g_epF + o);
            float4 vg = *(const float4*)(g_epG + o);
            f.x += vf.x + vg.x; f.y += vf.y + vg.y; f.z += vf.z + vg.z; f.w += vf.w + vg.w;
        }
        float4 gt = *(const float4*)&sGT[il][j4 * 4];
        float4 e = make_float4(f.x + gt.x, f.y + gt.y, f.z + gt.z, f.w + gt.w);
        *(float4*)(g_energy + ((size_t)(b * CC + i)) * CC + j4 * 4) = e;
        float mx = fmaxf(fmaxf(e.x, e.y), fmaxf(e.z, e.w));
        #pragma unroll
        for (int o = 16; o; o >>= 1) mx = fmaxf(mx, __shfl_xor_sync(0xffffffffu, mx, o));
        float e0 = mx - e.x, e1 = mx - e.y, e2 = mx - e.z, e3 = mx - e.w;
        float m2 = fmaxf(fmaxf(e0, e1), fmaxf(e2, e3));
        #pragma unroll
        for (int o = 16; o; o >>= 1) m2 = fmaxf(m2, __shfl_xor_sync(0xffffffffu, m2, o));
        float p0 = expf(e0 - m2), p1 = expf(e1 - m2), p2 = expf(e2 - m2), p3 = expf(e3 - m2);
        float s = (p0 + p1) + (p2 + p3);
        #pragma unroll
        for (int o = 16; o; o >>= 1) s += __shfl_xor_sync(0xffffffffu, s, o);
        float inv = 1.f / s;
        *(float4*)(g_attn + ((size_t)(b * CC + i)) * CC + j4 * 4) =
            make_float4(p0 * inv, p1 * inv, p2 * inv, p3 * inv);
    }
}

// ---- kernel 2: BN stats partials --------------------------------------------
__global__ void __launch_bounds__(256) k_stats1() {
    int cs = blockIdx.x, b = blockIdx.y, t = threadIdx.x, lane = t & 31, w = t >> 5;
    extern __shared__ float sms[];
    float* sE = sms;
    float* sA = sms + 16384;
    float* sR = sms + 16384 + 1024;
    const float4* Eg = (const float4*)(g_energy + (size_t)b * CC * CC);
    for (int i = t; i < 4096; i += 256) ((float4*)sE)[i] = Eg[i];
    const float4* Ag = (const float4*)(g_attn + ((size_t)b * CC + cs * 8) * CC);
    if (t < 256) ((float4*)sA)[t] = Ag[t];
    if (t < 128) {
        float s = 0.f;
        #pragma unroll
        for (int ks = 0; ks < KS1; ks++) s += g_rspart[(b * KS1 + ks) * CC + t];
        sR[t] = s;
    }
    __syncthreads();

    float accT[4] = {0.f, 0.f, 0.f, 0.f};
    for (int k = 0; k < 128; k++) {
        float4 e = *(float4*)&sE[k * 128 + lane * 4];
        float a = sA[w * 128 + k];
        accT[0] += a * e.x; accT[1] += a * e.y;
        accT[2] += a * e.z; accT[3] += a * e.w;
    }
    float4 r4 = *(float4*)&sR[lane * 4];
    float4 a4 = *(float4*)&sA[w * 128 + lane * 4];
    float l2 = accT[0] * a4.x + accT[1] * a4.y + accT[2] * a4.z + accT[3] * a4.w;
    float l1 = r4.x * a4.x + r4.y * a4.y + r4.z * a4.z + r4.w * a4.w;
    #pragma unroll
    for (int o = 16; o; o >>= 1) {
        l1 += __shfl_xor_sync(0xffffffffu, l1, o);
        l2 += __shfl_xor_sync(0xffffffffu, l2, o);
    }
    if (lane == 0) {
        g_part1[b * CC + cs * 8 + w] = l1;
        g_part2[b * CC + cs * 8 + w] = l2;
    }
}

// ---- kernel 3: out GEMM — R14 structure, conv-free (blobs via cp.async) -----
// smem: A limbs 4x16K @0 | blob ring 4x32K @65536 | s_scale @196608 | s_shift @197120
__global__ void __launch_bounds__(256) k_out_mma(const float* __restrict__ x,
                                                 float* __restrict__ out,
                                                 const float* __restrict__ gamma,
                                                 const float* __restrict__ bn_w,
                                                 const float* __restrict__ bn_b) {
    extern __shared__ char smraw[];
    char* sm = (char*)(((unsigned long long)smraw + 1023) & ~1023ULL);
    unsigned sb = smem_u32(sm);
    int t = threadIdx.x, lane = t & 31, wid = t >> 5;
    int nb = blockIdx.x, b = blockIdx.y;  // nb: 8 chunks of 2048 cols
    size_t xrow = (size_t)b * CC * HW;
    float* s_scale = (float*)(sm + 196608);
    float* s_shift = (float*)(sm + 197120);
    int wm = (wid >> 1) * 32, wn = (wid & 1) * 32;
    int g = lane >> 2, tg = lane & 3;

    // ---- prologue: scale/shift (fused stats2) ----
    if (t < 128) {
        float a1 = 0.f, a2 = 0.f;
        #pragma unroll
        for (int bb = 0; bb < BB; bb++) { a1 += g_part1[bb * CC + t]; a2 += g_part2[bb * CC + t]; }
        float gg = gamma[0];
        float invN = 1.f / (float)((size_t)BB * HW);
        float mean = gg * a1 * invN;
        float ey2 = gg * gg * a2 * invN;
        float rstd = rsqrtf(ey2 - mean * mean + 1e-5f);
        float w = bn_w[t];
        s_scale[t] = gg * rstd * w;
        s_shift[t] = bn_b[t] - mean * rstd * w;
    }
    __syncthreads();
    // ---- prologue: attn -> A limb tiles ----
    #pragma unroll
    for (int i2 = 0; i2 < 8; i2++) {
        int seg = t + 256 * i2;
        int row = seg >> 4, jp = seg & 15;
        int jhalf = jp >> 3, part = jp & 7;
        const float4* ap = (const float4*)(g_attn + ((size_t)(b * CC + row)) * CC + jp * 8);
        float4 v0 = ap[0], v1 = ap[1];
        float sc = s_scale[row];
        float fl[8] = {v0.x * sc, v0.y * sc, v0.z * sc, v0.w * sc,
                       v1.x * sc, v1.y * sc, v1.z * sc, v1.w * sc};
        unsigned so = swz((unsigned)(row * 128 + part * 16));
        conv8r(fl, sm + jhalf * 16384 + so, sm + (2 + jhalf) * 16384 + so);
    }
    __syncthreads();

    // hoist A limb0 fragments (64 regs)
    unsigned A0h[8][2][4];
    #pragma unroll
    for (int ksp = 0; ksp < 8; ksp++) {
        int jhalf = ksp >> 2;
        unsigned kb = (unsigned)((ksp & 3) * 32 + (lane >> 4) * 16);
        #pragma unroll
        for (int mt = 0; mt < 2; mt++) {
            unsigned off = swz((unsigned)((wm + mt * 16 + (lane & 15)) * 128) + kb);
            ldsm4(sb + jhalf * 16384 + off, A0h[ksp][mt]);
        }
    }

    // blob loads: 32 KB linear copy into ring slot (it & 3)
    #define B_LOAD(it) do { \
        unsigned _db = sb + 65536 + ((it) & 3) * 32768; \
        const char* _src = g_lb + ((size_t)b * 256 + nb * 32 + (it)) * 32768; \
        _Pragma("unroll") \
        for (int _i = 0; _i < 8; _i++) { \
            int _o = (t + 256 * _i) * 16; \
            CPA(_db + _o, _src + _o); \
        } \
        CPA_COMMIT(); \
    } while (0)

    B_LOAD(0);
    B_LOAD(1);
    CPA_WAIT1();     // blob 0 done
    __syncthreads();

    for (int it = 0; it < 32; it++) {
        int slot = it & 3;
        if (it + 2 < 32) B_LOAD(it + 2);
        size_t gx = xrow + (size_t)nb * 2048 + it * 64;

        // prefetch x for epilogue (latency hidden under MMA)
        float2 xp0[2][4], xp1[2][4];
        #pragma unroll
        for (int mt = 0; mt < 2; mt++) {
            int i0 = wm + mt * 16 + g;
            #pragma unroll
            for (int nf = 0; nf < 4; nf++) {
                int col = wn + nf * 8 + tg * 2;
                xp0[mt][nf] = *(const float2*)(x + gx + (size_t)i0 * HW + col);
                xp1[mt][nf] = *(const float2*)(x + gx + (size_t)(i0 + 8) * HW + col);
            }
        }

        float acc[2][4][4];
        #pragma unroll
        for (int mt = 0; mt < 2; mt++)
            #pragma unroll
            for (int nf = 0; nf < 4; nf++)
                #pragma unroll
                for (int c = 0; c < 4; c++) acc[mt][nf][c] = 0.f;

        unsigned Bt0 = sb + 65536 + slot * 32768;
        unsigned Bt1 = Bt0 + 16384;
        #pragma unroll
        for (int ksp = 0; ksp < 8; ksp++) {
            unsigned A1t[2][4];
            {
                int jhalf = ksp >> 2;
                unsigned kb = (unsigned)((ksp & 3) * 32 + (lane >> 4) * 16);
                #pragma unroll
                for (int mt = 0; mt < 2; mt++) {
                    unsigned off = swz((unsigned)((wm + mt * 16 + (lane & 15)) * 128) + kb);
                    ldsm4(sb + (2 + jhalf) * 16384 + off, A1t[mt]);
                }
            }
            int jrow = ksp * 16 + ((lane >> 3) & 1) * 8 + (lane & 7);
            #pragma unroll
            for (int f = 0; f < 2; f++) {
                int ncol = wn + f * 16 + ((lane >> 4) & 1) * 8;
                unsigned offb = swz((unsigned)(jrow * 128 + ncol * 2));
                unsigned B0[4], B1[4];
                ldsm4t(Bt0 + offb, B0);
                ldsm4t(Bt1 + offb, B1);
                #pragma unroll
                for (int s = 0; s < 2; s++) {
                    float* c0 = acc[0][f * 2 + s];
                    float* c1 = acc[1][f * 2 + s];
                    mma16816(c0, A0h[ksp][0], B0[s * 2], B0[s * 2 + 1]);
                    mma16816(c0, A0h[ksp][0], B1[s * 2], B1[s * 2 + 1]);
                    mma16816(c0, A1t[0], B0[s * 2], B0[s * 2 + 1]);
                    mma16816(c1, A0h[ksp][1], B0[s * 2], B0[s * 2 + 1]);
                    mma16816(c1, A0h[ksp][1], B1[s * 2], B1[s * 2 + 1]);
                    mma16816(c1, A1t[1], B0[s * 2], B0[s * 2 + 1]);
                }
            }
        }

        // epilogue: acc + shift + x, direct stores
        #pragma unroll
        for (int mt = 0; mt < 2; mt++) {
            int i0 = wm + mt * 16 + g;
            float sh0 = s_shift[i0], sh1 = s_shift[i0 + 8];
            #pragma unroll
            for (int nf = 0; nf < 4; nf++) {
                int col = wn + nf * 8 + tg * 2;
                *(float2*)(out + gx + (size_t)i0 * HW + col) =
                    make_float2(acc[mt][nf][0] + sh0 + xp0[mt][nf].x,
                                acc[mt][nf][1] + sh0 + xp0[mt][nf].y);
                *(float2*)(out + gx + (size_t)(i0 + 8) * HW + col) =
                    make_float2(acc[mt][nf][2] + sh1 + xp1[mt][nf].x,
                                acc[mt][nf][3] + sh1 + xp1[mt][nf].y);
            }
        }

        if (it + 2 < 32) CPA_WAIT1();       // blob it+1 done
        else if (it + 1 < 32) CPA_WAIT0();
        __syncthreads();                     // publish blob it+1; slot reuse safe
    }
    #undef B_LOAD
}

extern "C" void kernel_launch(void* const* d_in, const int* in_sizes, int n_in,
                              void* d_out, int out_size) {
    const float* x = (const float*)d_in[0];
    const float* gamma = (const float*)d_in[1];
    const float* bn_w = (const float*)d_in[2];
    const float* bn_b = (const float*)d_in[3];
    float* out = (float*)d_out;

    int smE = 65536 + 65536 + 4096 + 1024;    // ~133 KB
    int smS = (16384 + 1024 + 128) * 4 + 256; // ~68.8 KB
    int smO = 196608 + 1024 + 1024;           // ~194 KB
    cudaFuncSetAttribute(k_energy_mma, cudaFuncAttributeMaxDynamicSharedMemorySize, smE);
    cudaFuncSetAttribute(k_stats1, cudaFuncAttributeMaxDynamicSharedMemorySize, smS);
    cudaFuncSetAttribute(k_out_mma, cudaFuncAttributeMaxDynamicSharedMemorySize, smO);

    k_energy_mma<<<dim3(KS1, BB), 256, smE>>>(x);                 // 0
    k_redsoft<<<dim3(4, BB), 256>>>();                            // 1
    k_stats1<<<dim3(16, BB), 256, smS>>>();                       // 2
    k_out_mma<<<dim3(8, BB), 256, smO>>>(x, out, gamma, bn_w, bn_b);  // 3 (profiled)
}

// round 17
// speedup vs baseline: 1.2553x; 1.2553x over previous
#include <cuda_runtime.h>
#include <cuda_fp16.h>
#include <math.h>

#define BB 16
#define CC 128
#define HW 16384
#define KS1 8
#define KSEG (HW / KS1)  // 2048

__device__ float g_energy[BB * CC * CC];
__device__ float g_epF[BB * KS1 * CC * CC];
__device__ float g_epG[BB * KS1 * CC * CC];
__device__ float g_attn[BB * CC * CC];
__device__ float g_rspart[BB * KS1 * CC];
__device__ float g_part1[BB * CC];
__device__ float g_part2[BB * CC];

__device__ __forceinline__ unsigned smem_u32(const void* p) {
    unsigned a;
    asm("{ .reg .u64 t; cvta.to.shared.u64 t, %1; cvt.u32.u64 %0, t; }" : "=r"(a) : "l"(p));
    return a;
}
__device__ __forceinline__ unsigned swz(unsigned o) { return o ^ ((o >> 3) & 0x70); }

#define CPA(dst, src) asm volatile("cp.async.ca.shared.global [%0], [%1], 16;" :: "r"(dst), "l"(src))
#define CPA_COMMIT()  asm volatile("cp.async.commit_group;" ::: "memory")
#define CPA_WAIT0()   asm volatile("cp.async.wait_group 0;" ::: "memory")
#define CPA_WAIT1()   asm volatile("cp.async.wait_group 1;" ::: "memory")

__device__ __forceinline__ void ldsm4(unsigned a, unsigned r[4]) {
    asm volatile("ldmatrix.sync.aligned.m8n8.x4.shared.b16 {%0,%1,%2,%3}, [%4];"
                 : "=r"(r[0]), "=r"(r[1]), "=r"(r[2]), "=r"(r[3]) : "r"(a));
}
__device__ __forceinline__ void ldsm4t(unsigned a, unsigned r[4]) {
    asm volatile("ldmatrix.sync.aligned.m8n8.x4.trans.shared.b16 {%0,%1,%2,%3}, [%4];"
                 : "=r"(r[0]), "=r"(r[1]), "=r"(r[2]), "=r"(r[3]) : "r"(a));
}
// fp16 MMA, fp32 accumulate
__device__ __forceinline__ void mma16816(float c[4], const unsigned a[4], unsigned b0, unsigned b1) {
    asm volatile("mma.sync.aligned.m16n8k16.row.col.f32.f16.f16.f32 "
                 "{%0,%1,%2,%3}, {%4,%5,%6,%7}, {%8,%9}, {%0,%1,%2,%3};"
                 : "+f"(c[0]), "+f"(c[1]), "+f"(c[2]), "+f"(c[3])
                 : "r"(a[0]), "r"(a[1]), "r"(a[2]), "r"(a[3]), "r"(b0), "r"(b1));
}

// 8 fp32 -> fp16 limb0 (16B) + fp16 limb1 residual (16B); returns elem sum
__device__ __forceinline__ float conv8h(const float* fl, char* d0, char* d1) {
    unsigned p[4], q[4];
    #pragma unroll
    for (int k = 0; k < 4; k++) {
        float lo = fl[2 * k], hi = fl[2 * k + 1];
        unsigned pk;
        asm("cvt.rn.f16x2.f32 %0, %1, %2;" : "=r"(pk) : "f"(hi), "f"(lo));
        __half2 h2 = *(__half2*)&pk;
        float rlo = lo - __half2float(__low2half(h2));
        float rhi = hi - __half2float(__high2half(h2));
        unsigned qk;
        asm("cvt.rn.f16x2.f32 %0, %1, %2;" : "=r"(qk) : "f"(rhi), "f"(rlo));
        p[k] = pk; q[k] = qk;
    }
    *(uint4*)d0 = make_uint4(p[0], p[1], p[2], p[3]);
    *(uint4*)d1 = make_uint4(q[0], q[1], q[2], q[3]);
    return ((fl[0] + fl[1]) + (fl[2] + fl[3])) + ((fl[4] + fl[5]) + (fl[6] + fl[7]));
}
// 8 fp32 -> single fp16 limb (16B), no residual
__device__ __forceinline__ void conv8a(const float* fl, char* d0) {
    unsigned p[4];
    #pragma unroll
    for (int k = 0; k < 4; k++)
        asm("cvt.rn.f16x2.f32 %0, %1, %2;" : "=r"(p[k]) : "f"(fl[2 * k + 1]), "f"(fl[2 * k]));
    *(uint4*)d0 = make_uint4(p[0], p[1], p[2], p[3]);
}

// ---- kernel 0: energy, fp16 limbs: F = q0 q0^T, G = q0 q1^T -----------------
__global__ void __launch_bounds__(256) k_energy_mma(const float* __restrict__ x) {
    extern __shared__ char smraw[];
    char* sm = (char*)(((unsigned long long)smraw + 1023) & ~1023ULL);
    unsigned sb = smem_u32(sm);
    int t = threadIdx.x, lane = t & 31, wid = t >> 5;
    int ks = blockIdx.x, b = blockIdx.y;
    size_t rowbase = (size_t)b * CC * HW + (size_t)ks * KSEG;
    int wm = (wid >> 2) * 64, wn = (wid & 3) * 32;
    float* s_rs = (float*)(sm + 131072);
    float rsacc[4] = {0.f, 0.f, 0.f, 0.f};

    float accF[4][4][4], accG[4][4][4];
    #pragma unroll
    for (int mt = 0; mt < 4; mt++)
        #pragma unroll
        for (int nt = 0; nt < 4; nt++)
            #pragma unroll
            for (int c = 0; c < 4; c++) { accF[mt][nt][c] = 0.f; accG[mt][nt][c] = 0.f; }

    #define X_LOAD(ch) do { \
        unsigned _db = sb + ((ch) & 1) * 32768; \
        _Pragma("unroll") \
        for (int _i = 0; _i < 4; _i++) { \
            int _seg = t + 256 * _i; \
            int _row = _seg >> 3, _part = _seg & 7; \
            const float* _s = x + rowbase + (size_t)_row * HW + (ch) * 64 + _part * 8; \
            CPA(_db + _row * 256 + _part * 32, _s); \
            CPA(_db + _row * 256 + _part * 32 + 16, _s + 4); \
        } \
        CPA_COMMIT(); \
    } while (0)

    #define X_CONV(ch) do { \
        char* _st = sm + ((ch) & 1) * 32768; \
        char* _lb = sm + 65536 + ((ch) & 1) * 32768; \
        _Pragma("unroll") \
        for (int _i = 0; _i < 4; _i++) { \
            int _seg = t + 256 * _i; \
            int _row = _seg >> 3, _part = _seg & 7; \
            unsigned _so = swz((unsigned)(_row * 128 + _part * 16)); \
            const float* _f = (const float*)(_st + _row * 256 + _part * 32); \
            rsacc[_i] += conv8h(_f, _lb + _so, _lb + 16384 + _so); \
        } \
    } while (0)

    X_LOAD(0);
    X_LOAD(1);
    CPA_WAIT1();
    X_CONV(0);
    __syncthreads();

    for (int ch = 0; ch < 32; ch++) {
        if (ch + 2 < 32) X_LOAD(ch + 2);

        unsigned b0t = sb + 65536 + (ch & 1) * 32768;
        unsigned b1t = b0t + 16384;
        #pragma unroll
        for (int kk = 0; kk < 4; kk++) {
            int kbyte = kk * 32;
            unsigned A[4][4];
            #pragma unroll
            for (int mt = 0; mt < 4; mt++) {
                unsigned off = swz((unsigned)((wm + mt * 16 + (lane & 15)) * 128 + kbyte + (lane >> 4) * 16));
                ldsm4(b0t + off, A[mt]);
            }
            unsigned B0[2][4], B1[2][4];
            #pragma unroll
            for (int nt = 0; nt < 2; nt++) {
                int row = wn + nt * 16 + ((lane >> 4) & 1) * 8 + (lane & 7);
                int kb = kbyte + ((lane >> 3) & 1) * 16;
                unsigned off = swz((unsigned)(row * 128 + kb));
                ldsm4(b0t + off, B0[nt]);
                ldsm4(b1t + off, B1[nt]);
            }
            #pragma unroll
            for (int mt = 0; mt < 4; mt++)
                #pragma unroll
                for (int nt = 0; nt < 2; nt++)
                    #pragma unroll
                    for (int s = 0; s < 2; s++) {
                        mma16816(accF[mt][nt * 2 + s], A[mt], B0[nt][s * 2], B0[nt][s * 2 + 1]);
                        mma16816(accG[mt][nt * 2 + s], A[mt], B1[nt][s * 2], B1[nt][s * 2 + 1]);
                    }
        }

        if (ch + 1 < 32) {
            if (ch + 2 < 32) CPA_WAIT1(); else CPA_WAIT0();
            X_CONV(ch + 1);
        }
        __syncthreads();
    }
    #undef X_LOAD
    #undef X_CONV

    #pragma unroll
    for (int i = 0; i < 4; i++) s_rs[t + 256 * i] = rsacc[i];
    __syncthreads();
    if (t < 128) {
        float s = 0.f;
        #pragma unroll
        for (int k = 0; k < 8; k++) s += s_rs[t * 8 + k];
        g_rspart[(b * KS1 + ks) * CC + t] = s;
    }

    size_t pbase = ((size_t)(b * KS1 + ks)) * CC * CC;
    int g = lane >> 2, tg = lane & 3;
    #pragma unroll
    for (int mt = 0; mt < 4; mt++)
        #pragma unroll
        for (int nt = 0; nt < 4; nt++) {
            int i0 = wm + mt * 16 + g, j = wn + nt * 8 + tg * 2;
            *(float2*)(g_epF + pbase + (size_t)i0 * CC + j) = make_float2(accF[mt][nt][0], accF[mt][nt][1]);
            *(float2*)(g_epF + pbase + (size_t)(i0 + 8) * CC + j) = make_float2(accF[mt][nt][2], accF[mt][nt][3]);
            *(float2*)(g_epG + pbase + (size_t)i0 * CC + j) = make_float2(accG[mt][nt][0], accG[mt][nt][1]);
            *(float2*)(g_epG + pbase + (size_t)(i0 + 8) * CC + j) = make_float2(accG[mt][nt][2], accG[mt][nt][3]);
        }
}

// ---- kernel 1: fused E = F + G + G^T  AND softmax ---------------------------
__global__ void k_redsoft() {
    int islab = blockIdx.x, b = blockIdx.y, t = threadIdx.x;
    __shared__ float sGT[32][132];
    #pragma unroll
    for (int r = 0; r < 4; r++) {
        int idx = t + 256 * r;
        int j = idx >> 3, c4 = idx & 7;
        float4 s = make_float4(0.f, 0.f, 0.f, 0.f);
        #pragma unroll
        for (int ks = 0; ks < KS1; ks++) {
            float4 v = *(const float4*)(g_epG + (((size_t)(b * KS1 + ks) * CC + j)) * CC + islab * 32 + c4 * 4);
            s.x += v.x; s.y += v.y; s.z += v.z; s.w += v.w;
        }
        sGT[c4 * 4 + 0][j] = s.x;
        sGT[c4 * 4 + 1][j] = s.y;
        sGT[c4 * 4 + 2][j] = s.z;
        sGT[c4 * 4 + 3][j] = s.w;
    }
    __syncthreads();
    #pragma unroll
    for (int r = 0; r < 4; r++) {
        int idx = t + 256 * r;
        int il = idx >> 5, j4 = idx & 31;
        int i = islab * 32 + il;
        float4 f = make_float4(0.f, 0.f, 0.f, 0.f);
        #pragma unroll
        for (int ks = 0; ks < KS1; ks++) {
            size_t o = (((size_t)(b * KS1 + ks) * CC + i)) * CC + j4 * 4;
            float4 vf = *(const float4*)(g_epF + o);
            float4 vg = *(const float4*)(g_epG + o);
            f.x += vf.x + vg.x; f.y += vf.y + vg.y; f.z += vf.z + vg.z; f.w += vf.w + vg.w;
        }
        float4 gt = *(const float4*)&sGT[il][j4 * 4];
        float4 e = make_float4(f.x + gt.x, f.y + gt.y, f.z + gt.z, f.w + gt.w);
        *(float4*)(g_energy + ((size_t)(b * CC + i)) * CC + j4 * 4) = e;
        float mx = fmaxf(fmaxf(e.x, e.y), fmaxf(e.z, e.w));
        #pragma unroll
        for (int o = 16; o; o >>= 1) mx = fmaxf(mx, __shfl_xor_sync(0xffffffffu, mx, o));
        float e0 = mx - e.x, e1 = mx - e.y, e2 = mx - e.z, e3 = mx - e.w;
        float m2 = fmaxf(fmaxf(e0, e1), fmaxf(e2, e3));
        #pragma unroll
        for (int o = 16; o; o >>= 1) m2 = fmaxf(m2, __shfl_xor_sync(0xffffffffu, m2, o));
        float p0 = expf(e0 - m2), p1 = expf(e1 - m2), p2 = expf(e2 - m2), p3 = expf(e3 - m2);
        float s = (p0 + p1) + (p2 + p3);
        #pragma unroll
        for (int o = 16; o; o >>= 1) s += __shfl_xor_sync(0xffffffffu, s, o);
        float inv = 1.f / s;
        *(float4*)(g_attn + ((size_t)(b * CC + i)) * CC + j4 * 4) =
            make_float4(p0 * inv, p1 * inv, p2 * inv, p3 * inv);
    }
}

// ---- kernel 2: BN stats partials --------------------------------------------
__global__ void __launch_bounds__(256) k_stats1() {
    int cs = blockIdx.x, b = blockIdx.y, t = threadIdx.x, lane = t & 31, w = t >> 5;
    extern __shared__ float sms[];
    float* sE = sms;
    float* sA = sms + 16384;
    float* sR = sms + 16384 + 1024;
    const float4* Eg = (const float4*)(g_energy + (size_t)b * CC * CC);
    for (int i = t; i < 4096; i += 256) ((float4*)sE)[i] = Eg[i];
    const float4* Ag = (const float4*)(g_attn + ((size_t)b * CC + cs * 8) * CC);
    if (t < 256) ((float4*)sA)[t] = Ag[t];
    if (t < 128) {
        float s = 0.f;
        #pragma unroll
        for (int ks = 0; ks < KS1; ks++) s += g_rspart[(b * KS1 + ks) * CC + t];
        sR[t] = s;
    }
    __syncthreads();

    float accT[4] = {0.f, 0.f, 0.f, 0.f};
    for (int k = 0; k < 128; k++) {
        float4 e = *(float4*)&sE[k * 128 + lane * 4];
        float a = sA[w * 128 + k];
        accT[0] += a * e.x; accT[1] += a * e.y;
        accT[2] += a * e.z; accT[3] += a * e.w;
    }
    float4 r4 = *(float4*)&sR[lane * 4];
    float4 a4 = *(float4*)&sA[w * 128 + lane * 4];
    float l2 = accT[0] * a4.x + accT[1] * a4.y + accT[2] * a4.z + accT[3] * a4.w;
    float l1 = r4.x * a4.x + r4.y * a4.y + r4.z * a4.z + r4.w * a4.w;
    #pragma unroll
    for (int o = 16; o; o >>= 1) {
        l1 += __shfl_xor_sync(0xffffffffu, l1, o);
        l2 += __shfl_xor_sync(0xffffffffu, l2, o);
    }
    if (lane == 0) {
        g_part1[b * CC + cs * 8 + w] = l1;
        g_part2[b * CC + cs * 8 + w] = l2;
    }
}

// ---- kernel 3: out GEMM — fp16: A = fp16(scale*attn) 1 limb, B = q 2 limbs --
// smem: A tiles 2x16K @0 | limb ring 2x32K @32768 | s_scale @98304 | s_shift @98816
__global__ void __launch_bounds__(256) k_out_mma(const float* __restrict__ x,
                                                 float* __restrict__ out,
                                                 const float* __restrict__ gamma,
                                                 const float* __restrict__ bn_w,
                                                 const float* __restrict__ bn_b) {
    extern __shared__ char smraw[];
    char* sm = (char*)(((unsigned long long)smraw + 1023) & ~1023ULL);
    unsigned sb = smem_u32(sm);
    int t = threadIdx.x, lane = t & 31, wid = t >> 5;
    int nb = blockIdx.x, b = blockIdx.y;  // nb: 8 chunks of 2048 cols
    size_t xrow = (size_t)b * CC * HW;
    float* s_scale = (float*)(sm + 98304);
    float* s_shift = (float*)(sm + 98816);
    int wm = (wid >> 1) * 32, wn = (wid & 1) * 32;
    int g = lane >> 2, tg = lane & 3;

    // ---- prologue: scale/shift ----
    if (t < 128) {
        float a1 = 0.f, a2 = 0.f;
        #pragma unroll
        for (int bb = 0; bb < BB; bb++) { a1 += g_part1[bb * CC + t]; a2 += g_part2[bb * CC + t]; }
        float gg = gamma[0];
        float invN = 1.f / (float)((size_t)BB * HW);
        float mean = gg * a1 * invN;
        float ey2 = gg * gg * a2 * invN;
        float rstd = rsqrtf(ey2 - mean * mean + 1e-5f);
        float w = bn_w[t];
        s_scale[t] = gg * rstd * w;
        s_shift[t] = bn_b[t] - mean * rstd * w;
    }
    __syncthreads();
    // ---- prologue: attn -> single-limb fp16 A tiles ----
    #pragma unroll
    for (int i2 = 0; i2 < 8; i2++) {
        int seg = t + 256 * i2;
        int row = seg >> 4, jp = seg & 15;
        int jhalf = jp >> 3, part = jp & 7;
        const float4* ap = (const float4*)(g_attn + ((size_t)(b * CC + row)) * CC + jp * 8);
        float4 v0 = ap[0], v1 = ap[1];
        float sc = s_scale[row];
        float fl[8] = {v0.x * sc, v0.y * sc, v0.z * sc, v0.w * sc,
                       v1.x * sc, v1.y * sc, v1.z * sc, v1.w * sc};
        unsigned so = swz((unsigned)(row * 128 + part * 16));
        conv8a(fl, sm + jhalf * 16384 + so);
    }
    __syncthreads();

    // hoist A fragments (single limb, 64 regs)
    unsigned A0h[8][2][4];
    #pragma unroll
    for (int ksp = 0; ksp < 8; ksp++) {
        int jhalf = ksp >> 2;
        unsigned kb = (unsigned)((ksp & 3) * 32 + (lane >> 4) * 16);
        #pragma unroll
        for (int mt = 0; mt < 2; mt++) {
            unsigned off = swz((unsigned)((wm + mt * 16 + (lane & 15)) * 128) + kb);
            ldsm4(sb + jhalf * 16384 + off, A0h[ksp][mt]);
        }
    }

    float4 buf[8];
    #define OX_LDG(it) do { \
        size_t _nbase = (size_t)nb * 2048 + (it) * 64; \
        _Pragma("unroll") \
        for (int _i = 0; _i < 4; _i++) { \
            int _seg = t + 256 * _i; \
            int _row = _seg >> 3, _part = _seg & 7; \
            const float4* _p = (const float4*)(x + xrow + (size_t)_row * HW + _nbase + _part * 8); \
            buf[2 * _i] = _p[0]; \
            buf[2 * _i + 1] = _p[1]; \
        } \
    } while (0)
    #define OX_CST(it) do { \
        char* _lb = sm + 32768 + ((it) & 1) * 32768; \
        _Pragma("unroll") \
        for (int _i = 0; _i < 4; _i++) { \
            int _seg = t + 256 * _i; \
            int _row = _seg >> 3, _part = _seg & 7; \
            unsigned _so = swz((unsigned)(_row * 128 + _part * 16)); \
            float4 _a = buf[2 * _i], _b = buf[2 * _i + 1]; \
            float _fl[8] = {_a.x, _a.y, _a.z, _a.w, _b.x, _b.y, _b.z, _b.w}; \
            conv8h(_fl, _lb + _so, _lb + 16384 + _so); \
        } \
    } while (0)

    OX_LDG(0);
    OX_CST(0);
    OX_LDG(1);
    __syncthreads();

    for (int it = 0; it < 32; it++) {
        int slot = it & 1;
        size_t gx = xrow + (size_t)nb * 2048 + it * 64;

        // prefetch x for epilogue (latency hidden under MMA)
        float2 xp0[2][4], xp1[2][4];
        #pragma unroll
        for (int mt = 0; mt < 2; mt++) {
            int i0 = wm + mt * 16 + g;
            #pragma unroll
            for (int nf = 0; nf < 4; nf++) {
                int col = wn + nf * 8 + tg * 2;
                xp0[mt][nf] = *(const float2*)(x + gx + (size_t)i0 * HW + col);
                xp1[mt][nf] = *(const float2*)(x + gx + (size_t)(i0 + 8) * HW + col);
            }
        }

        float acc[2][4][4];
        #pragma unroll
        for (int mt = 0; mt < 2; mt++)
            #pragma unroll
            for (int nf = 0; nf < 4; nf++)
                #pragma unroll
                for (int c = 0; c < 4; c++) acc[mt][nf][c] = 0.f;

        unsigned Bt0 = sb + 32768 + slot * 32768;
        unsigned Bt1 = Bt0 + 16384;
        #pragma unroll
        for (int ksp = 0; ksp < 8; ksp++) {
            int jrow = ksp * 16 + ((lane >> 3) & 1) * 8 + (lane & 7);
            #pragma unroll
            for (int f = 0; f < 2; f++) {
                int ncol = wn + f * 16 + ((lane >> 4) & 1) * 8;
                unsigned offb = swz((unsigned)(jrow * 128 + ncol * 2));
                unsigned B0[4], B1[4];
                ldsm4t(Bt0 + offb, B0);
                ldsm4t(Bt1 + offb, B1);
                #pragma unroll
                for (int mt = 0; mt < 2; mt++)
                    #pragma unroll
                    for (int s = 0; s < 2; s++) {
                        float* c = acc[mt][f * 2 + s];
                        mma16816(c, A0h[ksp][mt], B0[s * 2], B0[s * 2 + 1]);
                        mma16816(c, A0h[ksp][mt], B1[s * 2], B1[s * 2 + 1]);
                    }
            }
        }

        // convert next chunk (overlaps HMMA drain), then prefetch chunk it+2
        if (it + 1 < 32) OX_CST(it + 1);
        if (it + 2 < 32) OX_LDG(it + 2);

        // epilogue: acc + shift + x, direct stores
        #pragma unroll
        for (int mt = 0; mt < 2; mt++) {
            int i0 = wm + mt * 16 + g;
            float sh0 = s_shift[i0], sh1 = s_shift[i0 + 8];
            #pragma unroll
            for (int nf = 0; nf < 4; nf++) {
                int col = wn + nf * 8 + tg * 2;
                *(float2*)(out + gx + (size_t)i0 * HW + col) =
                    make_float2(acc[mt][nf][0] + sh0 + xp0[mt][nf].x,
                                acc[mt][nf][1] + sh0 + xp0[mt][nf].y);
                *(float2*)(out + gx + (size_t)(i0 + 8) * HW + col) =
                    make_float2(acc[mt][nf][2] + sh1 + xp1[mt][nf].x,
                                acc[mt][nf][3] + sh1 + xp1[mt][nf].y);
            }
        }
        __syncthreads();  // limbs(it+1) published; slot reuse safe
    }
    #undef OX_LDG
    #undef OX_CST
}

extern "C" void kernel_launch(void* const* d_in, const int* in_sizes, int n_in,
                              void* d_out, int out_size) {
    const float* x = (const float*)d_in[0];
    const float* gamma = (const float*)d_in[1];
    const float* bn_w = (const float*)d_in[2];
    const float* bn_b = (const float*)d_in[3];
    float* out = (float*)d_out;

    int smE = 65536 + 65536 + 4096 + 1024;    // ~133 KB
    int smS = (16384 + 1024 + 128) * 4 + 256; // ~68.8 KB
    int smO = 98304 + 1024 + 1024;            // ~98 KB
    cudaFuncSetAttribute(k_energy_mma, cudaFuncAttributeMaxDynamicSharedMemorySize, smE);
    cudaFuncSetAttribute(k_stats1, cudaFuncAttributeMaxDynamicSharedMemorySize, smS);
    cudaFuncSetAttribute(k_out_mma, cudaFuncAttributeMaxDynamicSharedMemorySize, smO);

    k_energy_mma<<<dim3(KS1, BB), 256, smE>>>(x);                 // 0
    k_redsoft<<<dim3(4, BB), 256>>>();                            // 1
    k_stats1<<<dim3(16, BB), 256, smS>>>();                       // 2
    k_out_mma<<<dim3(8, BB), 256, smO>>>(x, out, gamma, bn_w, bn_b);  // 3 (profiled)
}